// round 10
// baseline (speedup 1.0000x reference)
#include <cuda_runtime.h>
#include <cuda_fp16.h>
#include <cstdint>
#include <cstddef>

// ============================================================
// GAT attention head, N=8192, IN_F=128, OUT_F=64
//  h = X@W ; e = LeakyReLU(fs_i + fd_j) masked by adj ; softmax ; P@h ; elu
//
// exp(LR(fs+fd)) = max(E_i*E_j, G_i*G_j), E=exp(f), G=exp(0.2f)
// -> no transcendental in N^2 loop. Fixed-max softmax -> single pass;
// fp16 P/h via mma.sync.m16n8k16, fp32 accumulators + denominators.
//
// sigma j-permutation: k=2q->j=4q, k=2q+1->j=4q+1, k=2q+8->j=4q+2, k=2q+9->j=4q+3
// adj/H/EG staged via cp.async, THREE buffers, prefetch distance 2:
// each tile's load gets ~2 compute phases to complete -> no exposed wait.
// 512-thread CTA (16 warps): warp pair shares a 16-row group, splits the
// 64 features (32 each); P compute duplicated (cheap), H LDS halved.
// ============================================================

#define NT 8192
#define IN_FEAT 128
#define OUT_FEAT 64
#define SPLITS 8
#define JSPAN (NT / SPLITS)      // 1024
#define JTILE 64
#define NTILES (JSPAN / JTILE)   // 16
#define ADJROW 320               // 64*4 + 64 pad: LDS.128 conflict-free
#define HROW 160                 // 64*2 + 32 pad: LDS.64 conflict-free

#define ADJ_BYTES (128 * ADJROW)         // 40960
#define H_BYTES   (OUT_FEAT * HROW)      // 10240
#define EG_BYTES  (JTILE * 8)            // 512
#define OFF_ADJ(i) ((i) * ADJ_BYTES)
#define OFF_H(i)   (3 * ADJ_BYTES + (i) * H_BYTES)
#define OFF_EG(i)  (3 * ADJ_BYTES + 3 * H_BYTES + (i) * EG_BYTES)
#define ATTN_SMEM  (3 * ADJ_BYTES + 3 * H_BYTES + 3 * EG_BYTES)  // 155136

#define PREP_WS   0
#define PREP_XS   (IN_FEAT * OUT_FEAT * 4)            // 32768
#define PREP_HS   (PREP_XS + 32 * IN_FEAT * 4)        // 49152
#define HS_STRIDE 34
#define PREP_SMEM (PREP_HS + OUT_FEAT * HS_STRIDE * 2) // 53504

// ---------------- scratch (static device arrays; no allocation) ----------
__device__ __half g_ht[OUT_FEAT * NT];          // h transposed fp16: [f][j]
__device__ float2 g_EGs[NT];
__device__ float2 g_EGd[NT];
__device__ float  g_num[SPLITS * NT * OUT_FEAT];
__device__ float  g_den[SPLITS * NT];

// ---------------- helpers ------------------------------------------------
__device__ __forceinline__ uint32_t smem_u32(const void* p) {
    uint32_t a;
    asm("{ .reg .u64 t; cvta.to.shared.u64 t, %1; cvt.u32.u64 %0, t; }"
        : "=r"(a) : "l"(p));
    return a;
}
__device__ __forceinline__ void cp16(uint32_t dst, const void* src) {
    asm volatile("cp.async.cg.shared.global [%0], [%1], 16;" :: "r"(dst), "l"(src));
}
__device__ __forceinline__ void cp8(uint32_t dst, const void* src) {
    asm volatile("cp.async.ca.shared.global [%0], [%1], 8;" :: "r"(dst), "l"(src));
}
#define CP_COMMIT() asm volatile("cp.async.commit_group;" ::: "memory")
#define CP_WAIT(n)  asm volatile("cp.async.wait_group %0;" :: "n"(n) : "memory")

__device__ __forceinline__ void mma16816(float* d, uint32_t a0, uint32_t a1,
                                         uint32_t a2, uint32_t a3,
                                         uint32_t b0, uint32_t b1) {
    asm volatile(
        "mma.sync.aligned.m16n8k16.row.col.f32.f16.f16.f32 "
        "{%0,%1,%2,%3}, {%4,%5,%6,%7}, {%8,%9}, {%0,%1,%2,%3};"
        : "+f"(d[0]), "+f"(d[1]), "+f"(d[2]), "+f"(d[3])
        : "r"(a0), "r"(a1), "r"(a2), "r"(a3), "r"(b0), "r"(b1));
}
__device__ __forceinline__ uint32_t packh2(float x, float y) {
    __half2 h = __floats2half2_rn(x, y);
    return *reinterpret_cast<uint32_t*>(&h);
}

// =========================================================================
// Kernel 1: h = X@W ; EG tables ; h^T fp16 (coalesced via smem transpose).
// 256 blocks x 256 threads; 32 rows/block; warp owns 4 rows.
// =========================================================================
__global__ void __launch_bounds__(256) prep_kernel(const float* __restrict__ x,
                                                   const float* __restrict__ W,
                                                   const float* __restrict__ a) {
    extern __shared__ __align__(16) char sm[];
    float*  Ws = (float*)(sm + PREP_WS);
    float*  xs = (float*)(sm + PREP_XS);
    __half* hs = (__half*)(sm + PREP_HS);   // [64 f][34]

    int tid = threadIdx.x;
    int i0 = blockIdx.x * 32;

    {
        const float4* W4 = (const float4*)W;
        float4* Ws4 = (float4*)Ws;
#pragma unroll
        for (int u = 0; u < 8; u++) Ws4[tid + u * 256] = W4[tid + u * 256];
        const float4* x4 = (const float4*)(x + (size_t)i0 * IN_FEAT);
        float4* xs4 = (float4*)xs;
#pragma unroll
        for (int u = 0; u < 4; u++) xs4[tid + u * 256] = x4[tid + u * 256];
    }
    __syncthreads();

    int w = tid >> 5, l = tid & 31;
    float acc[4][2];
#pragma unroll
    for (int rr = 0; rr < 4; rr++) { acc[rr][0] = 0.f; acc[rr][1] = 0.f; }

#pragma unroll 4
    for (int k4 = 0; k4 < IN_FEAT; k4 += 4) {
        float2 wv[4];
#pragma unroll
        for (int kk = 0; kk < 4; kk++)
            wv[kk] = *(const float2*)&Ws[(k4 + kk) * OUT_FEAT + 2 * l];
#pragma unroll
        for (int rr = 0; rr < 4; rr++) {
            float4 xv = *(const float4*)&xs[(w * 4 + rr) * IN_FEAT + k4];
            acc[rr][0] = fmaf(xv.x, wv[0].x, acc[rr][0]);
            acc[rr][1] = fmaf(xv.x, wv[0].y, acc[rr][1]);
            acc[rr][0] = fmaf(xv.y, wv[1].x, acc[rr][0]);
            acc[rr][1] = fmaf(xv.y, wv[1].y, acc[rr][1]);
            acc[rr][0] = fmaf(xv.z, wv[2].x, acc[rr][0]);
            acc[rr][1] = fmaf(xv.z, wv[2].y, acc[rr][1]);
            acc[rr][0] = fmaf(xv.w, wv[3].x, acc[rr][0]);
            acc[rr][1] = fmaf(xv.w, wv[3].y, acc[rr][1]);
        }
    }

#pragma unroll
    for (int rr = 0; rr < 4; rr++) {
        int il = w * 4 + rr;
        hs[(2 * l) * HS_STRIDE + il]     = __float2half(acc[rr][0]);
        hs[(2 * l + 1) * HS_STRIDE + il] = __float2half(acc[rr][1]);
    }

    float a0 = a[2 * l], a1 = a[2 * l + 1];
    float a2 = a[OUT_FEAT + 2 * l], a3 = a[OUT_FEAT + 2 * l + 1];
#pragma unroll
    for (int rr = 0; rr < 4; rr++) {
        float s = acc[rr][0] * a0 + acc[rr][1] * a1;
        float d = acc[rr][0] * a2 + acc[rr][1] * a3;
#pragma unroll
        for (int off = 16; off; off >>= 1) {
            s += __shfl_xor_sync(0xFFFFFFFFu, s, off);
            d += __shfl_xor_sync(0xFFFFFFFFu, d, off);
        }
        if (l == 0) {
            int i = i0 + w * 4 + rr;
            g_EGs[i] = make_float2(expf(s), expf(0.2f * s));
            g_EGd[i] = make_float2(expf(d), expf(0.2f * d));
        }
    }
    __syncthreads();

#pragma unroll
    for (int u = 0; u < 4; u++) {
        int id = tid + u * 256;
        int f = id >> 4, c = id & 15;
        uint32_t v = *(const uint32_t*)&hs[f * HS_STRIDE + 2 * c];
        *(uint32_t*)&g_ht[(size_t)f * NT + i0 + 2 * c] = v;
    }
}

// =========================================================================
// Kernel 2: fused masked-softmax attention; 3-stage cp.async pipeline.
// grid (64, SPLITS) = 512 CTAs, 512 threads, 1 CTA/SM (155 KB smem).
// Warp pair (wg) covers 16 rows; half selects 32-feature slice.
// =========================================================================
__global__ void __launch_bounds__(512) attn_kernel(const int* __restrict__ adj) {
    extern __shared__ __align__(16) char sm[];
    uint32_t sb = smem_u32(sm);

    int tid = threadIdx.x, w = tid >> 5, lane = tid & 31;
    int wg = w >> 1, half = w & 1;
    int r = lane >> 2, q = lane & 3;
    int i0 = blockIdx.x * 128;
    int split = blockIdx.y;
    int jbase = split * JSPAN;

    int R0 = i0 + wg * 16 + r;
    float2 egs0 = g_EGs[R0];
    float2 egs1 = g_EGs[R0 + 8];

    float acc[4][4];
#pragma unroll
    for (int nt = 0; nt < 4; nt++)
#pragma unroll
        for (int v = 0; v < 4; v++) acc[nt][v] = 0.f;
    float ds0 = 0.f, ds1 = 0.f;

    // stage one tile: adj (128x64 int) + H (64x64 fp16) + EG (64 float2)
    auto issue_tile = [&](int buf, int j0) {
        uint32_t ab = sb + OFF_ADJ(buf);
        uint32_t hb = sb + OFF_H(buf);
        uint32_t eb = sb + OFF_EG(buf);
#pragma unroll
        for (int u = 0; u < 4; u++) {           // adj: 2048 chunks / 512 thr
            int id = tid + u * 512;
            int row = id >> 4, c = id & 15;
            cp16(ab + row * ADJROW + c * 16,
                 &adj[(size_t)(i0 + row) * NT + j0 + c * 4]);
        }
        {                                       // H: 512 chunks
            int f = tid >> 3, c = tid & 7;
            cp16(hb + f * HROW + c * 16,
                 &g_ht[(size_t)f * NT + j0 + c * 8]);
        }
        if (tid < JTILE) cp8(eb + tid * 8, &g_EGd[j0 + tid]);
        CP_COMMIT();
    };

    issue_tile(0, jbase);
    issue_tile(1, jbase + JTILE);

    for (int t = 0; t < NTILES; t++) {
        int b = t % 3;
        __syncthreads();                        // all warps done with tile t-1
        if (t + 2 < NTILES) { issue_tile((t + 2) % 3, jbase + (t + 2) * JTILE); CP_WAIT(2); }
        else if (t + 1 < NTILES) { CP_WAIT(1); }
        else { CP_WAIT(0); }
        __syncthreads();                        // tile t visible to all warps

        const char* ab = sm + OFF_ADJ(b);
        const char* hb = sm + OFF_H(b);
        const float2* eb = (const float2*)(sm + OFF_EG(b));

#pragma unroll
        for (int kk = 0; kk < 4; kk++) {
            int jloc = kk * 16 + 4 * q;
            int4 avA = *(const int4*)(ab + (wg * 16 + r) * ADJROW + kk * 64 + q * 16);
            int4 avB = *(const int4*)(ab + (wg * 16 + r + 8) * ADJROW + kk * 64 + q * 16);
            float4 egA = *(const float4*)&eb[jloc];
            float4 egB = *(const float4*)&eb[jloc + 2];

            float p00 = avA.x ? fmaxf(egs0.x * egA.x, egs0.y * egA.y) : 0.f;
            float p01 = avA.y ? fmaxf(egs0.x * egA.z, egs0.y * egA.w) : 0.f;
            float p02 = avA.z ? fmaxf(egs0.x * egB.x, egs0.y * egB.y) : 0.f;
            float p03 = avA.w ? fmaxf(egs0.x * egB.z, egs0.y * egB.w) : 0.f;
            float p10 = avB.x ? fmaxf(egs1.x * egA.x, egs1.y * egA.y) : 0.f;
            float p11 = avB.y ? fmaxf(egs1.x * egA.z, egs1.y * egA.w) : 0.f;
            float p12 = avB.z ? fmaxf(egs1.x * egB.x, egs1.y * egB.y) : 0.f;
            float p13 = avB.w ? fmaxf(egs1.x * egB.z, egs1.y * egB.w) : 0.f;

            ds0 += (p00 + p01) + (p02 + p03);
            ds1 += (p10 + p11) + (p12 + p13);

            uint32_t A0 = packh2(p00, p01);
            uint32_t A1 = packh2(p10, p11);
            uint32_t A2 = packh2(p02, p03);
            uint32_t A3 = packh2(p12, p13);

            int ko = kk * 32 + q * 8;
#pragma unroll
            for (int nt = 0; nt < 4; nt++) {
                int f0 = (half * 4 + nt) * 8 + r;
                uint2 bb = *(const uint2*)(hb + f0 * HROW + ko);
                mma16816(acc[nt], A0, A1, A2, A3, bb.x, bb.y);
            }
        }
    }

    // denominator: reduce over the 4 lanes (q); write from half 0 only
    ds0 += __shfl_xor_sync(0xFFFFFFFFu, ds0, 1);
    ds0 += __shfl_xor_sync(0xFFFFFFFFu, ds0, 2);
    ds1 += __shfl_xor_sync(0xFFFFFFFFu, ds1, 1);
    ds1 += __shfl_xor_sync(0xFFFFFFFFu, ds1, 2);
    if (q == 0 && half == 0) {
        g_den[(size_t)split * NT + R0]     = ds0;
        g_den[(size_t)split * NT + R0 + 8] = ds1;
    }

    float* gn = &g_num[(size_t)split * NT * OUT_FEAT];
#pragma unroll
    for (int nt = 0; nt < 4; nt++) {
        int col = (half * 4 + nt) * 8 + q * 2;
        *(float2*)&gn[(size_t)R0 * OUT_FEAT + col]       = make_float2(acc[nt][0], acc[nt][1]);
        *(float2*)&gn[(size_t)(R0 + 8) * OUT_FEAT + col] = make_float2(acc[nt][2], acc[nt][3]);
    }
}

// =========================================================================
// Kernel 3: combine split partials, divide, elu
// =========================================================================
__global__ void __launch_bounds__(256) finalize_kernel(float* __restrict__ out) {
    size_t idx = (size_t)blockIdx.x * 256 + threadIdx.x;
    size_t i = idx >> 6;
    float num = 0.f, den = 0.f;
#pragma unroll
    for (int s = 0; s < SPLITS; s++) {
        num += g_num[(size_t)s * NT * OUT_FEAT + idx];
        den += g_den[(size_t)s * NT + i];
    }
    den = fmaxf(den, 1e-30f);
    float v = num / den;
    out[idx] = v > 0.f ? v : expm1f(v);
}

// =========================================================================
extern "C" void kernel_launch(void* const* d_in, const int* in_sizes, int n_in,
                              void* d_out, int out_size) {
    const float* x   = (const float*)d_in[0];
    const int*   adj = (const int*)d_in[1];
    const float* W   = (const float*)d_in[2];
    const float* a   = (const float*)d_in[3];
    float* out = (float*)d_out;

    cudaFuncSetAttribute(prep_kernel, cudaFuncAttributeMaxDynamicSharedMemorySize,
                         PREP_SMEM);
    cudaFuncSetAttribute(attn_kernel, cudaFuncAttributeMaxDynamicSharedMemorySize,
                         ATTN_SMEM);

    prep_kernel<<<NT / 32, 256, PREP_SMEM>>>(x, W, a);
    attn_kernel<<<dim3(64, SPLITS), 512, ATTN_SMEM>>>(adj);
    finalize_kernel<<<(NT * OUT_FEAT) / 256, 256>>>(out);
}

// round 11
// speedup vs baseline: 1.4355x; 1.4355x over previous
#include <cuda_runtime.h>
#include <cuda_fp16.h>
#include <cstdint>
#include <cstddef>

// ============================================================
// GAT attention head, N=8192, IN_F=128, OUT_F=64
//  h = X@W ; e = LeakyReLU(fs_i + fd_j) masked by adj ; softmax ; P@h ; elu
//
// exp(LR(fs+fd)) = max(E_i*E_j, G_i*G_j), E=exp(f), G=exp(0.2f)
// -> no transcendental in N^2 loop. Fixed-max softmax -> single pass;
// fp16 P/h via mma.sync.m16n8k16, fp32 accumulators + denominators.
//
// PERSISTENT scheduling: 296 CTAs (2/SM x 148) own static contiguous ranges
// of the 8192 global tiles (64 row-blocks x 128 j-tiles of 64) -> 27-28
// tiles per CTA -> 98.9% wave utilization (vs 86.5% for 512 equal CTAs).
// On row-block change a CTA flushes its accumulators via atomicAdd.
// adj/H/EG staged via cp.async double buffer (proven R9 pipeline body).
// ============================================================

#define NT 8192
#define IN_FEAT 128
#define OUT_FEAT 64
#define JTILE 64
#define TILES_PER_RB (NT / JTILE)     // 128
#define NUM_RB (NT / 128)             // 64
#define TOTAL_TILES (NUM_RB * TILES_PER_RB)  // 8192
#define WORKERS 296
#define ADJROW 320               // 64*4 + 64 pad: LDS.128 conflict-free
#define HROW 160                 // 64*2 + 32 pad: LDS.64 conflict-free

#define ADJ_BYTES (128 * ADJROW)         // 40960
#define H_BYTES   (OUT_FEAT * HROW)      // 10240
#define EG_BYTES  (JTILE * 8)            // 512
#define OFF_ADJ(i) ((i) * ADJ_BYTES)
#define OFF_H(i)   (2 * ADJ_BYTES + (i) * H_BYTES)
#define OFF_EG(i)  (2 * ADJ_BYTES + 2 * H_BYTES + (i) * EG_BYTES)
#define ATTN_SMEM  (2 * ADJ_BYTES + 2 * H_BYTES + 2 * EG_BYTES)  // 103424

#define PREP_WS   0
#define PREP_XS   (IN_FEAT * OUT_FEAT * 4)            // 32768
#define PREP_HS   (PREP_XS + 32 * IN_FEAT * 4)        // 49152
#define HS_STRIDE 34
#define PREP_SMEM (PREP_HS + OUT_FEAT * HS_STRIDE * 2) // 53504

// ---------------- scratch (static device arrays; no allocation) ----------
__device__ __half g_ht[OUT_FEAT * NT];     // h transposed fp16: [f][j]
__device__ float2 g_EGs[NT];
__device__ float2 g_EGd[NT];
__device__ float  g_num[NT * OUT_FEAT];    // atomic accumulators
__device__ float  g_den[NT];

// ---------------- helpers ------------------------------------------------
__device__ __forceinline__ uint32_t smem_u32(const void* p) {
    uint32_t a;
    asm("{ .reg .u64 t; cvta.to.shared.u64 t, %1; cvt.u32.u64 %0, t; }"
        : "=r"(a) : "l"(p));
    return a;
}
__device__ __forceinline__ void cp16(uint32_t dst, const void* src) {
    asm volatile("cp.async.cg.shared.global [%0], [%1], 16;" :: "r"(dst), "l"(src));
}
__device__ __forceinline__ void cp8(uint32_t dst, const void* src) {
    asm volatile("cp.async.ca.shared.global [%0], [%1], 8;" :: "r"(dst), "l"(src));
}
#define CP_COMMIT() asm volatile("cp.async.commit_group;" ::: "memory")
#define CP_WAIT(n)  asm volatile("cp.async.wait_group %0;" :: "n"(n) : "memory")

__device__ __forceinline__ void mma16816(float* d, uint32_t a0, uint32_t a1,
                                         uint32_t a2, uint32_t a3,
                                         uint32_t b0, uint32_t b1) {
    asm volatile(
        "mma.sync.aligned.m16n8k16.row.col.f32.f16.f16.f32 "
        "{%0,%1,%2,%3}, {%4,%5,%6,%7}, {%8,%9}, {%0,%1,%2,%3};"
        : "+f"(d[0]), "+f"(d[1]), "+f"(d[2]), "+f"(d[3])
        : "r"(a0), "r"(a1), "r"(a2), "r"(a3), "r"(b0), "r"(b1));
}
__device__ __forceinline__ uint32_t packh2(float x, float y) {
    __half2 h = __floats2half2_rn(x, y);
    return *reinterpret_cast<uint32_t*>(&h);
}

// =========================================================================
// Kernel 0: zero the atomic accumulators
// =========================================================================
__global__ void __launch_bounds__(256) zero_kernel() {
    int gid = blockIdx.x * 256 + threadIdx.x;
    ((float4*)g_num)[gid] = make_float4(0.f, 0.f, 0.f, 0.f);
    if (gid < NT / 4)
        ((float4*)g_den)[gid] = make_float4(0.f, 0.f, 0.f, 0.f);
}

// =========================================================================
// Kernel 1: h = X@W ; EG tables ; h^T fp16 (coalesced via smem transpose).
// 256 blocks x 512 threads; 32 rows/block; warp owns 2 rows.
// =========================================================================
__global__ void __launch_bounds__(512) prep_kernel(const float* __restrict__ x,
                                                   const float* __restrict__ W,
                                                   const float* __restrict__ a) {
    extern __shared__ __align__(16) char sm[];
    float*  Ws = (float*)(sm + PREP_WS);
    float*  xs = (float*)(sm + PREP_XS);
    __half* hs = (__half*)(sm + PREP_HS);   // [64 f][34]

    int tid = threadIdx.x;
    int i0 = blockIdx.x * 32;

    {
        const float4* W4 = (const float4*)W;
        float4* Ws4 = (float4*)Ws;
#pragma unroll
        for (int u = 0; u < 4; u++) Ws4[tid + u * 512] = W4[tid + u * 512];
        const float4* x4 = (const float4*)(x + (size_t)i0 * IN_FEAT);
        float4* xs4 = (float4*)xs;
#pragma unroll
        for (int u = 0; u < 2; u++) xs4[tid + u * 512] = x4[tid + u * 512];
    }
    __syncthreads();

    int w = tid >> 5, l = tid & 31;       // warp w: rows 2w, 2w+1
    float acc[2][2];
#pragma unroll
    for (int rr = 0; rr < 2; rr++) { acc[rr][0] = 0.f; acc[rr][1] = 0.f; }

#pragma unroll 4
    for (int k4 = 0; k4 < IN_FEAT; k4 += 4) {
        float2 wv[4];
#pragma unroll
        for (int kk = 0; kk < 4; kk++)
            wv[kk] = *(const float2*)&Ws[(k4 + kk) * OUT_FEAT + 2 * l];
#pragma unroll
        for (int rr = 0; rr < 2; rr++) {
            float4 xv = *(const float4*)&xs[(w * 2 + rr) * IN_FEAT + k4];
            acc[rr][0] = fmaf(xv.x, wv[0].x, acc[rr][0]);
            acc[rr][1] = fmaf(xv.x, wv[0].y, acc[rr][1]);
            acc[rr][0] = fmaf(xv.y, wv[1].x, acc[rr][0]);
            acc[rr][1] = fmaf(xv.y, wv[1].y, acc[rr][1]);
            acc[rr][0] = fmaf(xv.z, wv[2].x, acc[rr][0]);
            acc[rr][1] = fmaf(xv.z, wv[2].y, acc[rr][1]);
            acc[rr][0] = fmaf(xv.w, wv[3].x, acc[rr][0]);
            acc[rr][1] = fmaf(xv.w, wv[3].y, acc[rr][1]);
        }
    }

#pragma unroll
    for (int rr = 0; rr < 2; rr++) {
        int il = w * 2 + rr;
        hs[(2 * l) * HS_STRIDE + il]     = __float2half(acc[rr][0]);
        hs[(2 * l + 1) * HS_STRIDE + il] = __float2half(acc[rr][1]);
    }

    float a0 = a[2 * l], a1 = a[2 * l + 1];
    float a2 = a[OUT_FEAT + 2 * l], a3 = a[OUT_FEAT + 2 * l + 1];
#pragma unroll
    for (int rr = 0; rr < 2; rr++) {
        float s = acc[rr][0] * a0 + acc[rr][1] * a1;
        float d = acc[rr][0] * a2 + acc[rr][1] * a3;
#pragma unroll
        for (int off = 16; off; off >>= 1) {
            s += __shfl_xor_sync(0xFFFFFFFFu, s, off);
            d += __shfl_xor_sync(0xFFFFFFFFu, d, off);
        }
        if (l == 0) {
            int i = i0 + w * 2 + rr;
            g_EGs[i] = make_float2(expf(s), expf(0.2f * s));
            g_EGd[i] = make_float2(expf(d), expf(0.2f * d));
        }
    }
    __syncthreads();

#pragma unroll
    for (int u = 0; u < 2; u++) {
        int id = tid + u * 512;
        int f = id >> 4, c = id & 15;
        uint32_t v = *(const uint32_t*)&hs[f * HS_STRIDE + 2 * c];
        *(uint32_t*)&g_ht[(size_t)f * NT + i0 + 2 * c] = v;
    }
}

// =========================================================================
// Kernel 2: fused masked-softmax attention, persistent static-range CTAs.
// grid 296, 256 threads, 2 CTAs/SM. Pipeline body identical to R9.
// =========================================================================
__global__ void __launch_bounds__(256) attn_kernel(const int* __restrict__ adj) {
    extern __shared__ __align__(16) char sm[];
    uint32_t sb = smem_u32(sm);

    int tid = threadIdx.x, w = tid >> 5, lane = tid & 31;
    int r = lane >> 2, q = lane & 3;
    int cta = blockIdx.x;

    int t0 = (int)(((long long)cta * TOTAL_TILES) / WORKERS);
    int t1 = (int)(((long long)(cta + 1) * TOTAL_TILES) / WORKERS);

    float acc[8][4];
#pragma unroll
    for (int nt = 0; nt < 8; nt++)
#pragma unroll
        for (int v = 0; v < 4; v++) acc[nt][v] = 0.f;
    float ds0 = 0.f, ds1 = 0.f;

    // stage tile t: adj (128x64 int) + H (64x64 fp16) + EG (64 float2)
    auto issue_tile = [&](int buf, int t) {
        int i0t = (t >> 7) * 128;
        int j0t = (t & 127) * JTILE;
        uint32_t ab = sb + OFF_ADJ(buf);
        uint32_t hb = sb + OFF_H(buf);
        uint32_t eb = sb + OFF_EG(buf);
#pragma unroll
        for (int u = 0; u < 8; u++) {           // adj: 2048 chunks / 256 thr
            int id = tid + u * 256;
            int row = id >> 4, c = id & 15;
            cp16(ab + row * ADJROW + c * 16,
                 &adj[(size_t)(i0t + row) * NT + j0t + c * 4]);
        }
#pragma unroll
        for (int u = 0; u < 2; u++) {           // H: 512 chunks
            int id = tid + u * 256;
            int f = id >> 3, c = id & 7;
            cp16(hb + f * HROW + c * 16,
                 &g_ht[(size_t)f * NT + j0t + c * 8]);
        }
        if (tid < JTILE) cp8(eb + tid * 8, &g_EGd[j0t + tid]);
        CP_COMMIT();
    };

    int cur_rb = t0 >> 7;
    float2 egs0 = g_EGs[cur_rb * 128 + w * 16 + r];
    float2 egs1 = g_EGs[cur_rb * 128 + w * 16 + r + 8];

    auto flush = [&](int rb) {
        float d0 = ds0, d1 = ds1;
        d0 += __shfl_xor_sync(0xFFFFFFFFu, d0, 1);
        d0 += __shfl_xor_sync(0xFFFFFFFFu, d0, 2);
        d1 += __shfl_xor_sync(0xFFFFFFFFu, d1, 1);
        d1 += __shfl_xor_sync(0xFFFFFFFFu, d1, 2);
        int R = rb * 128 + w * 16 + r;
        if (q == 0) {
            atomicAdd(&g_den[R], d0);
            atomicAdd(&g_den[R + 8], d1);
        }
#pragma unroll
        for (int nt = 0; nt < 8; nt++) {
            int col = nt * 8 + q * 2;
            atomicAdd(&g_num[(size_t)R * OUT_FEAT + col],           acc[nt][0]);
            atomicAdd(&g_num[(size_t)R * OUT_FEAT + col + 1],       acc[nt][1]);
            atomicAdd(&g_num[(size_t)(R + 8) * OUT_FEAT + col],     acc[nt][2]);
            atomicAdd(&g_num[(size_t)(R + 8) * OUT_FEAT + col + 1], acc[nt][3]);
            acc[nt][0] = acc[nt][1] = acc[nt][2] = acc[nt][3] = 0.f;
        }
        ds0 = 0.f; ds1 = 0.f;
    };

    issue_tile(t0 & 1, t0);

    for (int t = t0; t < t1; t++) {
        int b = t & 1;
        __syncthreads();                        // buffer b^1 free for prefetch
        if (t + 1 < t1) { issue_tile((t + 1) & 1, t + 1); CP_WAIT(1); }
        else            { CP_WAIT(0); }
        __syncthreads();                        // tile t visible to all warps

        int rb = t >> 7;
        if (rb != cur_rb) {                     // row-block change: flush
            flush(cur_rb);
            cur_rb = rb;
            egs0 = g_EGs[rb * 128 + w * 16 + r];
            egs1 = g_EGs[rb * 128 + w * 16 + r + 8];
        }

        const char* ab = sm + OFF_ADJ(b);
        const char* hb = sm + OFF_H(b);
        const float2* eb = (const float2*)(sm + OFF_EG(b));

#pragma unroll
        for (int kk = 0; kk < 4; kk++) {
            int jloc = kk * 16 + 4 * q;
            int4 avA = *(const int4*)(ab + (w * 16 + r) * ADJROW + kk * 64 + q * 16);
            int4 avB = *(const int4*)(ab + (w * 16 + r + 8) * ADJROW + kk * 64 + q * 16);
            float4 egA = *(const float4*)&eb[jloc];
            float4 egB = *(const float4*)&eb[jloc + 2];

            float p00 = avA.x ? fmaxf(egs0.x * egA.x, egs0.y * egA.y) : 0.f;
            float p01 = avA.y ? fmaxf(egs0.x * egA.z, egs0.y * egA.w) : 0.f;
            float p02 = avA.z ? fmaxf(egs0.x * egB.x, egs0.y * egB.y) : 0.f;
            float p03 = avA.w ? fmaxf(egs0.x * egB.z, egs0.y * egB.w) : 0.f;
            float p10 = avB.x ? fmaxf(egs1.x * egA.x, egs1.y * egA.y) : 0.f;
            float p11 = avB.y ? fmaxf(egs1.x * egA.z, egs1.y * egA.w) : 0.f;
            float p12 = avB.z ? fmaxf(egs1.x * egB.x, egs1.y * egB.y) : 0.f;
            float p13 = avB.w ? fmaxf(egs1.x * egB.z, egs1.y * egB.w) : 0.f;

            ds0 += (p00 + p01) + (p02 + p03);
            ds1 += (p10 + p11) + (p12 + p13);

            uint32_t A0 = packh2(p00, p01);
            uint32_t A1 = packh2(p10, p11);
            uint32_t A2 = packh2(p02, p03);
            uint32_t A3 = packh2(p12, p13);

            int ko = kk * 32 + q * 8;
#pragma unroll
            for (int nt = 0; nt < 8; nt++) {
                uint2 bb = *(const uint2*)(hb + (nt * 8 + r) * HROW + ko);
                mma16816(acc[nt], A0, A1, A2, A3, bb.x, bb.y);
            }
        }
    }

    flush(cur_rb);
}

// =========================================================================
// Kernel 3: divide + elu
// =========================================================================
__global__ void __launch_bounds__(256) finalize_kernel(float* __restrict__ out) {
    size_t idx = (size_t)blockIdx.x * 256 + threadIdx.x;
    size_t i = idx >> 6;
    float den = fmaxf(g_den[i], 1e-30f);
    float v = g_num[idx] / den;
    out[idx] = v > 0.f ? v : expm1f(v);
}

// =========================================================================
extern "C" void kernel_launch(void* const* d_in, const int* in_sizes, int n_in,
                              void* d_out, int out_size) {
    const float* x   = (const float*)d_in[0];
    const int*   adj = (const int*)d_in[1];
    const float* W   = (const float*)d_in[2];
    const float* a   = (const float*)d_in[3];
    float* out = (float*)d_out;

    cudaFuncSetAttribute(prep_kernel, cudaFuncAttributeMaxDynamicSharedMemorySize,
                         PREP_SMEM);
    cudaFuncSetAttribute(attn_kernel, cudaFuncAttributeMaxDynamicSharedMemorySize,
                         ATTN_SMEM);

    zero_kernel<<<(NT * OUT_FEAT) / 4 / 256, 256>>>();
    prep_kernel<<<NT / 32, 512, PREP_SMEM>>>(x, W, a);
    attn_kernel<<<WORKERS, 256, ATTN_SMEM>>>(adj);
    finalize_kernel<<<(NT * OUT_FEAT) / 256, 256>>>(out);
}